// round 12
// baseline (speedup 1.0000x reference)
#include <cuda_runtime.h>
#include <cuda_fp16.h>
#include <mma.h>
#include <math.h>
#include <stdint.h>

using namespace nvcuda;

#define B_WIN  4096
#define NT     49
#define CDIM   256
#define HEADS  8
#define HDIM   32
#define KQKV   768
#define MROWS  (B_WIN * NT)          /* 200704 = 128*1568 */
#define SCALE_F 0.17677669529663687f /* 32^-0.5 */

/* -------- scratch (allocation-free: __device__ globals) -------- */
__device__ __half g_xh[(size_t)MROWS * CDIM];    /* x in fp16            */
__device__ __half g_qkvh[(size_t)MROWS * KQKV];  /* qkv in fp16          */
__device__ __half g_oh[(size_t)MROWS * CDIM];    /* attn out in fp16     */
__device__ __half g_wh[(size_t)KQKV * CDIM];     /* qkv_w fp16           */
__device__ __half g_pwh[(size_t)CDIM * CDIM];    /* proj_w fp16          */

/* -------- cp.async helpers -------- */
__device__ __forceinline__ void cp_async16(void* smem_dst, const void* gmem_src) {
    unsigned sa = (unsigned)__cvta_generic_to_shared(smem_dst);
    asm volatile("cp.async.cg.shared.global [%0], [%1], 16;\n" :: "r"(sa), "l"(gmem_src));
}
__device__ __forceinline__ void cp_commit() {
    asm volatile("cp.async.commit_group;\n" ::: "memory");
}
template <int N>
__device__ __forceinline__ void cp_wait() {
    asm volatile("cp.async.wait_group %0;\n" :: "n"(N) : "memory");
}
/* named barrier over 128 threads (one half-block) */
#define NBAR(id) asm volatile("bar.sync %0, 128;" :: "r"(id) : "memory")

/* -------- FMA-pipe exp -------- */
__device__ __forceinline__ float exp_fast(float x) {
    float y = fmaxf(x, -87.0f) * 1.44269504f;
    float t = y + 12582912.0f;                    /* 1.5*2^23 RN magic */
    int   e = __float_as_int(t) - 0x4B400000;
    float f = y - (t - 12582912.0f);
    float p =              1.33336e-3f;
    p = fmaf(p, f, 9.61813e-3f);
    p = fmaf(p, f, 5.55041e-2f);
    p = fmaf(p, f, 2.40227e-1f);
    p = fmaf(p, f, 6.93147e-1f);
    p = fmaf(p, f, 1.0f);
    return p * __int_as_float(0x3F800000 + (e << 23));
}

/* =====================================================================
 * fp32 -> fp16 convert
 * ===================================================================*/
__global__ __launch_bounds__(256) void f2h_kernel(
    const float* __restrict__ in, __half* __restrict__ out, int n)
{
    int i = (blockIdx.x * 256 + threadIdx.x) * 4;
    if (i < n) {
        float4 v = *(const float4*)&in[i];
        *(half2*)&out[i]     = __floats2half2_rn(v.x, v.y);
        *(half2*)&out[i + 2] = __floats2half2_rn(v.z, v.w);
    }
}

/* =====================================================================
 * GEMM v5 (round-9 config; only change: __stwt on fp32 output path).
 * Block 128x64, BK=64, cp.async double buffer, 128 thr = 4 warps.
 * ===================================================================*/
#define G5_STRIDE 72
#define G5_TILEH  ((128 + 64) * G5_STRIDE)
#define GEMMH_SMEM (2 * G5_TILEH * 2 + 128)

template <int OUT_HALF>
__global__ __launch_bounds__(128) void gemm_h_kernel(
    const __half* __restrict__ A, const __half* __restrict__ W,
    const float* __restrict__ bias, void* __restrict__ Cv,
    int Nld, int K)
{
    extern __shared__ char smem_raw[];
    __half* Sh = (__half*)smem_raw;

    const int tid  = threadIdx.x;
    const int warp = tid >> 5;
    const int m0   = blockIdx.y * 128;
    const int n0   = blockIdx.x * 64;
    const int nk   = K >> 6;

    const int cr = tid >> 3;
    const int cc = tid & 7;

#pragma unroll
    for (int st = 0; st < 2; st++) {
        if (st < nk) {
            int kc = st * 64;
            __half* dst = Sh + st * G5_TILEH;
#pragma unroll
            for (int i = 0; i < 8; i++) {
                int r = cr + i * 16;
                cp_async16(&dst[r * G5_STRIDE + cc * 8],
                           &A[(size_t)(m0 + r) * K + kc + cc * 8]);
            }
#pragma unroll
            for (int i = 0; i < 4; i++) {
                int r = cr + i * 16;
                cp_async16(&dst[(128 + r) * G5_STRIDE + cc * 8],
                           &W[(size_t)(n0 + r) * K + kc + cc * 8]);
            }
        }
        cp_commit();
    }

    wmma::fragment<wmma::accumulator, 16, 16, 16, float> c[2][4];
#pragma unroll
    for (int i = 0; i < 2; i++)
#pragma unroll
        for (int j = 0; j < 4; j++)
            wmma::fill_fragment(c[i][j], 0.0f);

    for (int kt = 0; kt < nk; kt++) {
        cp_wait<1>();
        __syncthreads();
        const __half* Ab = Sh + (kt & 1) * G5_TILEH;
        const __half* Bb = Ab + 128 * G5_STRIDE;

#pragma unroll
        for (int ks = 0; ks < 4; ks++) {
            wmma::fragment<wmma::matrix_a, 16, 16, 16, __half, wmma::row_major> a[2];
#pragma unroll
            for (int i = 0; i < 2; i++)
                wmma::load_matrix_sync(a[i],
                    &Ab[(warp * 32 + i * 16) * G5_STRIDE + ks * 16], G5_STRIDE);
#pragma unroll
            for (int j = 0; j < 4; j++) {
                wmma::fragment<wmma::matrix_b, 16, 16, 16, __half, wmma::col_major> b;
                wmma::load_matrix_sync(b, &Bb[(j * 16) * G5_STRIDE + ks * 16], G5_STRIDE);
                wmma::mma_sync(c[0][j], a[0], b, c[0][j]);
                wmma::mma_sync(c[1][j], a[1], b, c[1][j]);
            }
        }
        __syncthreads();

        int kn = kt + 2;
        if (kn < nk) {
            int kc = kn * 64;
            __half* dst = Sh + (kt & 1) * G5_TILEH;
#pragma unroll
            for (int i = 0; i < 8; i++) {
                int r = cr + i * 16;
                cp_async16(&dst[r * G5_STRIDE + cc * 8],
                           &A[(size_t)(m0 + r) * K + kc + cc * 8]);
            }
#pragma unroll
            for (int i = 0; i < 4; i++) {
                int r = cr + i * 16;
                cp_async16(&dst[(128 + r) * G5_STRIDE + cc * 8],
                           &W[(size_t)(n0 + r) * K + kc + cc * 8]);
            }
        }
        cp_commit();
    }

    float* stg = (float*)smem_raw;
    __syncthreads();
#pragma unroll
    for (int i = 0; i < 2; i++)
#pragma unroll
        for (int j = 0; j < 4; j++)
            wmma::store_matrix_sync(&stg[(warp * 32 + i * 16) * 68 + j * 16],
                                    c[i][j], 68, wmma::mem_row_major);
    __syncthreads();

    const int cp2 = (tid & 31) << 1;
    const float b0 = bias[n0 + cp2];
    const float b1 = bias[n0 + cp2 + 1];
    if (OUT_HALF) {
        __half* Ch = (__half*)Cv;
#pragma unroll
        for (int k = 0; k < 32; k++) {
            int row = (tid + k * 128) >> 5;
            *(half2*)&Ch[(size_t)(m0 + row) * Nld + n0 + cp2] =
                __floats2half2_rn(stg[row * 68 + cp2] + b0,
                                  stg[row * 68 + cp2 + 1] + b1);
        }
    } else {
        /* final output: never re-read -> streaming stores */
        float* Cf = (float*)Cv;
#pragma unroll
        for (int k = 0; k < 32; k++) {
            int row = (tid + k * 128) >> 5;
            float2 o = make_float2(stg[row * 68 + cp2] + b0,
                                   stg[row * 68 + cp2 + 1] + b1);
            __stwt((float2*)&Cf[(size_t)(m0 + row) * Nld + n0 + cp2], o);
        }
    }
}

/* =====================================================================
 * Attention v8: one block = (window, head-pair), 256 threads.
 * Warps 0-3 process head h0, warps 4-7 process head h0+1 CONCURRENTLY.
 * Halves are fully decoupled: each issues its own cp.async group and
 * syncs only via named barrier (bar.sync 1/2, 128). No __syncthreads.
 * attn probs written with __stwt (never re-read).
 * ===================================================================*/
#define AT_STR  40                    /* halves per tile row       */
#define AT_TILE (64 * AT_STR)         /* 2560 halves per operand   */
#define AT_UNIT (3 * AT_TILE)         /* q|k|v per unit            */

__global__ __launch_bounds__(256, 3) void attn_kernel(
    const __half* __restrict__ qkv, const float* __restrict__ mask,
    const float* __restrict__ bias_table, float* __restrict__ attn_out,
    __half* __restrict__ o_out)
{
    __shared__ __half tiles[2 * AT_UNIT];     /* 30.7 KB */
    __shared__ float  ss[2][64 * 68];         /* 34.8 KB */
    __shared__ float  biasS[2][176];
    __shared__ int    tS[64];

    const int tid  = threadIdx.x;
    const int u    = tid >> 7;            /* half: 0 or 1      */
    const int ltid = tid & 127;           /* id within half    */
    const int warp = ltid >> 5;           /* warp within half  */
    const int lane = tid & 31;
    const int bar  = 1 + u;
    const int h0   = blockIdx.x * 2;
    const int b    = blockIdx.y;

    const __half* hbase = qkv + (size_t)b * NT * KQKV + (h0 + u) * HDIM;
    __half* dstu = tiles + u * AT_UNIT;
    const __half* qs_ = dstu;
    const __half* ks_ = dstu + AT_TILE;
    const __half* vs_ = dstu + 2 * AT_TILE;
    __half* ps = dstu;                    /* P overlay on dead q/k (4608<=5120) */
    float* sU = ss[u];

    /* each half issues cp.async for ITS unit: 49 rows x 12 x 16B chunks */
    for (int idx = ltid; idx < NT * 12; idx += 128) {
        int r    = idx / 12;
        int c    = idx - r * 12;
        int seg  = c >> 2;               /* 0=q 1=k 2=v */
        int off8 = (c & 3) * 8;
        cp_async16(&dstu[seg * AT_TILE + r * AT_STR + off8],
                   &hbase[(size_t)r * KQKV + seg * 256 + off8]);
    }
    cp_commit();

    /* overlapped fills (own half only; tS identical from both halves) */
    {
        half2 z = __floats2half2_rn(0.f, 0.f);
        half2* vpad = (half2*)(dstu + 2 * AT_TILE + NT * AT_STR);
        for (int i = ltid; i < 15 * (AT_STR / 2); i += 128) vpad[i] = z;
    }
    for (int r = ltid; r < 169; r += 128)
        biasS[u][r] = __ldg(&bias_table[r * HEADS + h0 + u]);
    if (ltid < 64) {
        int q7 = ltid / 7;
        tS[ltid] = q7 * 13 + (ltid - q7 * 7);
    }

    cp_wait<0>();
    NBAR(bar);

    /* S = Q K^T (64x64, K=32); warp -> 16-row slab */
    {
        wmma::fragment<wmma::accumulator, 16, 16, 16, float> sc[4];
#pragma unroll
        for (int j = 0; j < 4; j++) wmma::fill_fragment(sc[j], 0.0f);
#pragma unroll
        for (int ks = 0; ks < 2; ks++) {
            wmma::fragment<wmma::matrix_a, 16, 16, 16, __half, wmma::row_major> a;
            wmma::load_matrix_sync(a, &qs_[(warp * 16) * AT_STR + ks * 16], AT_STR);
#pragma unroll
            for (int j = 0; j < 4; j++) {
                wmma::fragment<wmma::matrix_b, 16, 16, 16, __half, wmma::col_major> bf;
                wmma::load_matrix_sync(bf, &ks_[(j * 16) * AT_STR + ks * 16], AT_STR);
                wmma::mma_sync(sc[j], a, bf, sc[j]);
            }
        }
#pragma unroll
        for (int j = 0; j < 4; j++)
            wmma::store_matrix_sync(&sU[(warp * 16) * 68 + j * 16], sc[j], 68,
                                    wmma::mem_row_major);
    }
    NBAR(bar);   /* S staged; this unit's q/k now dead */

    /* attn = S*scale + bias + mask */
    {
        const float* mwin = mask + (size_t)(b & 63) * NT * NT;
        const float* bb = biasS[u];
        for (int idx = ltid; idx < NT * NT; idx += 128) {
            int n = idx / NT, m = idx - n * NT;
            int rel = tS[n] - tS[m] + 84;
            sU[n * 68 + m] = sU[n * 68 + m] * SCALE_F + bb[rel] + mwin[idx];
        }
    }
    NBAR(bar);

    /* softmax: 2 threads per row */
    {
        int n = ltid >> 1, hf = ltid & 1;
        float* row = &sU[n * 68];
        float mx = -1e30f;
        for (int m = hf; m < NT; m += 2) mx = fmaxf(mx, row[m]);
        mx = fmaxf(mx, __shfl_xor_sync(0xffffffffu, mx, 1));
        float sum = 0.f;
        for (int m = hf; m < NT; m += 2) {
            float e = exp_fast(row[m] - mx);
            row[m] = e;
            sum += e;
        }
        sum += __shfl_xor_sync(0xffffffffu, sum, 1);
        float inv = 1.0f / sum;
        for (int m = hf; m < NT; m += 2) row[m] *= inv;
    }
    NBAR(bar);

    /* write attn probs (streaming) + build fp16 P (cols >= 49 zeroed) */
    {
        float* aout = attn_out + (size_t)(b * HEADS + h0 + u) * NT * NT;
        for (int idx = ltid; idx < 64 * 32; idx += 128) {
            int n = idx >> 5, m2 = (idx & 31) << 1;
            float v0 = (m2     < NT) ? sU[n * 68 + m2]     : 0.f;
            float v1 = (m2 + 1 < NT) ? sU[n * 68 + m2 + 1] : 0.f;
            *(half2*)&ps[n * 72 + m2] = __floats2half2_rn(v0, v1);
            if (n < NT) {
                if (m2     < NT) __stwt(&aout[n * NT + m2],     v0);
                if (m2 + 1 < NT) __stwt(&aout[n * NT + m2 + 1], v1);
            }
        }
    }
    NBAR(bar);

    /* O = P @ V; stage to own ss rows; warp-private store */
    {
        wmma::fragment<wmma::accumulator, 16, 16, 16, float> oc[2];
#pragma unroll
        for (int j = 0; j < 2; j++) wmma::fill_fragment(oc[j], 0.0f);
#pragma unroll
        for (int ks = 0; ks < 4; ks++) {
            wmma::fragment<wmma::matrix_a, 16, 16, 16, __half, wmma::row_major> a;
            wmma::load_matrix_sync(a, &ps[(warp * 16) * 72 + ks * 16], 72);
#pragma unroll
            for (int j = 0; j < 2; j++) {
                wmma::fragment<wmma::matrix_b, 16, 16, 16, __half, wmma::row_major> bf;
                wmma::load_matrix_sync(bf, &vs_[(ks * 16) * AT_STR + j * 16], AT_STR);
                wmma::mma_sync(oc[j], a, bf, oc[j]);
            }
        }
#pragma unroll
        for (int j = 0; j < 2; j++)
            wmma::store_matrix_sync(&sU[(warp * 16) * 68 + j * 16], oc[j], 68,
                                    wmma::mem_row_major);
        __syncwarp();
        __half* obase = o_out + (size_t)b * NT * CDIM + (h0 + u) * HDIM;
        for (int idx = lane; idx < 16 * 16; idx += 32) {
            int r = idx >> 4, d2 = (idx & 15) << 1, n = warp * 16 + r;
            if (n < NT)
                *(half2*)&obase[(size_t)n * CDIM + d2] =
                    __floats2half2_rn(sU[n * 68 + d2], sU[n * 68 + d2 + 1]);
        }
    }
}

/* ===================================================================*/
extern "C" void kernel_launch(void* const* d_in, const int* in_sizes, int n_in,
                              void* d_out, int out_size)
{
    const float* x          = (const float*)d_in[0];
    const float* mask       = (const float*)d_in[1];
    const float* qkv_w      = (const float*)d_in[2];
    const float* qkv_b      = (const float*)d_in[3];
    const float* proj_w     = (const float*)d_in[4];
    const float* proj_b     = (const float*)d_in[5];
    const float* bias_table = (const float*)d_in[6];

    float* out_part  = (float*)d_out;                       /* [200704][256] */
    float* attn_part = out_part + (size_t)MROWS * CDIM;     /* [32768][49][49] */

    __half *xh = nullptr, *qkvh = nullptr, *oh = nullptr, *wh = nullptr, *pwh = nullptr;
    cudaGetSymbolAddress((void**)&xh,   g_xh);
    cudaGetSymbolAddress((void**)&qkvh, g_qkvh);
    cudaGetSymbolAddress((void**)&oh,   g_oh);
    cudaGetSymbolAddress((void**)&wh,   g_wh);
    cudaGetSymbolAddress((void**)&pwh,  g_pwh);

    static int smem_set = 0;
    if (!smem_set) {
        cudaFuncSetAttribute(gemm_h_kernel<1>,
                             cudaFuncAttributeMaxDynamicSharedMemorySize, GEMMH_SMEM);
        cudaFuncSetAttribute(gemm_h_kernel<0>,
                             cudaFuncAttributeMaxDynamicSharedMemorySize, GEMMH_SMEM);
        smem_set = 1;
    }

    /* 0) fp16 conversions */
    f2h_kernel<<<(MROWS * CDIM / 4 + 255) / 256, 256>>>(x, xh, MROWS * CDIM);
    f2h_kernel<<<(KQKV * CDIM / 4 + 255) / 256, 256>>>(qkv_w, wh, KQKV * CDIM);
    f2h_kernel<<<(CDIM * CDIM / 4 + 255) / 256, 256>>>(proj_w, pwh, CDIM * CDIM);

    /* 1) QKV GEMM */
    gemm_h_kernel<1><<<dim3(KQKV / 64, MROWS / 128), 128, GEMMH_SMEM>>>(
        xh, wh, qkv_b, qkvh, KQKV, CDIM);

    /* 2) attention: one block per (window, head-pair), split halves */
    attn_kernel<<<dim3(HEADS / 2, B_WIN), 256>>>(
        qkvh, mask, bias_table, attn_part, oh);

    /* 3) proj GEMM */
    gemm_h_kernel<0><<<dim3(CDIM / 64, MROWS / 128), 128, GEMMH_SMEM>>>(
        oh, pwh, proj_b, out_part, CDIM, CDIM);
}